// round 1
// baseline (speedup 1.0000x reference)
#include <cuda_runtime.h>
#include <cstdint>

// Problem constants (fixed by the dataset)
#define NMAX 50000

// ---------------- scratch (static device globals; no allocation) ----------------
__device__ __align__(16) float g_P  [(size_t)NMAX * 128];  // projected features
__device__ __align__(16) float g_AGG[(size_t)NMAX * 128];  // aggregation target
__device__ __align__(16) float g_H  [(size_t)NMAX * 128];  // hidden activations
__device__ __align__(16) int   g_outdeg[NMAX + 8];
__device__ __align__(16) int   g_indeg [NMAX + 8];
__device__ __align__(16) float g_onorm [NMAX + 8];
__device__ __align__(16) float g_inorm [NMAX + 8];

// ---------------- small utility kernels ----------------
__global__ void k_zero_deg(int n4) {
    int i = blockIdx.x * blockDim.x + threadIdx.x;
    if (i < n4) {
        ((int4*)g_outdeg)[i] = make_int4(0, 0, 0, 0);
        ((int4*)g_indeg)[i]  = make_int4(0, 0, 0, 0);
    }
}

__global__ void k_zero_agg(int n4) {
    int i = blockIdx.x * blockDim.x + threadIdx.x;
    if (i < n4) ((float4*)g_AGG)[i] = make_float4(0.f, 0.f, 0.f, 0.f);
}

__global__ void k_degree(const int* __restrict__ src, const int* __restrict__ dst, int nE) {
    int i = blockIdx.x * blockDim.x + threadIdx.x;
    if (i < nE) {
        atomicAdd(&g_outdeg[src[i]], 1);
        atomicAdd(&g_indeg[dst[i]], 1);
    }
}

__global__ void k_norm(int n) {
    int i = blockIdx.x * blockDim.x + threadIdx.x;
    if (i < n) {
        g_onorm[i] = rsqrtf(fmaxf((float)g_outdeg[i], 1.f));
        g_inorm[i] = rsqrtf(fmaxf((float)g_indeg[i], 1.f));
    }
}

// ---------------- GEMM: P[r,:] = (X[r,:] * onorm[r]) @ W ----------------
// X is always [n,128]. W is [128, NCOUT], staged into smem padded to COLS.
// Tile: 64 rows x COLS cols per block, 256 threads.
template<int COLS, int NCOUT>
__global__ void __launch_bounds__(256)
k_gemm(const float* __restrict__ X, const float* __restrict__ W,
       float* __restrict__ P, int n) {
    extern __shared__ float sm[];
    float* Ws = sm;               // [128][COLS]
    float* Xs = sm + 128 * COLS;  // [64][132] (pad keeps 16B alignment)

    const int tid = threadIdx.x;
    const int r0  = blockIdx.x * 64;

    // stage W
    if (COLS == NCOUT) {
        for (int q = tid; q < 128 * COLS / 4; q += 256)
            ((float4*)Ws)[q] = ((const float4*)W)[q];
    } else {
        for (int q = tid; q < 128 * COLS; q += 256) {
            int k = q / COLS, c = q % COLS;
            Ws[q] = (c < NCOUT) ? W[k * NCOUT + c] : 0.f;
        }
    }
    // stage X tile, fused out_norm scaling
    for (int q = tid; q < 64 * 32; q += 256) {
        int r = q >> 5, c4 = q & 31;
        int gr = r0 + r;
        float4 v = make_float4(0.f, 0.f, 0.f, 0.f);
        if (gr < n) {
            v = ((const float4*)(X + (size_t)gr * 128))[c4];
            float s = g_onorm[gr];
            v.x *= s; v.y *= s; v.z *= s; v.w *= s;
        }
        *((float4*)(Xs + r * 132 + c4 * 4)) = v;
    }
    __syncthreads();

    constexpr int CG  = COLS / 4;   // col groups of 4
    constexpr int RGC = 256 / CG;   // row groups
    constexpr int RPT = 64 / RGC;   // rows per thread
    const int cg = tid % CG;
    const int rg = tid / CG;

    float acc[RPT][4];
#pragma unroll
    for (int i = 0; i < RPT; ++i)
#pragma unroll
        for (int j = 0; j < 4; ++j) acc[i][j] = 0.f;

    const float* xbase = Xs + rg * RPT * 132;
    const float4* wc = ((const float4*)Ws) + cg;
#pragma unroll 4
    for (int k = 0; k < 128; ++k) {
        float4 b = wc[k * CG];
#pragma unroll
        for (int i = 0; i < RPT; ++i) {
            float a = xbase[i * 132 + k];
            acc[i][0] = fmaf(a, b.x, acc[i][0]);
            acc[i][1] = fmaf(a, b.y, acc[i][1]);
            acc[i][2] = fmaf(a, b.z, acc[i][2]);
            acc[i][3] = fmaf(a, b.w, acc[i][3]);
        }
    }

#pragma unroll
    for (int i = 0; i < RPT; ++i) {
        int gr = r0 + rg * RPT + i;
        if (gr >= n) continue;
        if (COLS == NCOUT) {
            ((float4*)(P + (size_t)gr * NCOUT))[cg] =
                make_float4(acc[i][0], acc[i][1], acc[i][2], acc[i][3]);
        } else {
            int c = cg * 4;
#pragma unroll
            for (int j = 0; j < 4; ++j)
                if (c + j < NCOUT) P[(size_t)gr * NCOUT + c + j] = acc[i][j];
        }
    }
}

// ---------------- edge aggregation (vector reduction atomics) ----------------
// 128-dim: one warp per edge; lane handles one float4 (32*16B = full row).
__global__ void k_agg128(const int* __restrict__ src, const int* __restrict__ dst, int nE) {
    int w    = (blockIdx.x * blockDim.x + threadIdx.x) >> 5;
    int lane = threadIdx.x & 31;
    if (w >= nE) return;
    int s = __ldg(&src[w]);
    int d = __ldg(&dst[w]);
    float4 v = ((const float4*)(g_P + (size_t)s * 128))[lane];
    float4* p = ((float4*)(g_AGG + (size_t)d * 128)) + lane;
    asm volatile("red.global.add.v4.f32 [%0], {%1,%2,%3,%4};"
                 :: "l"(p), "f"(v.x), "f"(v.y), "f"(v.z), "f"(v.w) : "memory");
}

// 40-dim: thread t -> (edge, group); reads are fully contiguous (addr = t*16B).
__global__ void k_agg40(const int* __restrict__ src, const int* __restrict__ dst, int nE) {
    int t = blockIdx.x * blockDim.x + threadIdx.x;
    if (t >= nE * 10) return;
    int e = t / 10, g = t % 10;
    int s = __ldg(&src[e]);
    int d = __ldg(&dst[e]);
    float4 v = ((const float4*)(g_P + (size_t)s * 40))[g];
    float4* p = ((float4*)(g_AGG + (size_t)d * 40)) + g;
    asm volatile("red.global.add.v4.f32 [%0], {%1,%2,%3,%4};"
                 :: "l"(p), "f"(v.x), "f"(v.y), "f"(v.z), "f"(v.w) : "memory");
}

// ---------------- epilogue: out = AGG * in_norm + b, optional relu ----------------
template<bool RELU, int C4>
__global__ void k_epilogue(const float* __restrict__ b, float* __restrict__ out, int n) {
    int idx = blockIdx.x * blockDim.x + threadIdx.x;
    if (idx >= n * C4) return;
    int row = idx / C4;
    int c   = idx - row * C4;
    float4 a  = ((const float4*)g_AGG)[idx];
    float  s  = g_inorm[row];
    float4 bb = ((const float4*)b)[c];
    float4 r;
    r.x = fmaf(a.x, s, bb.x);
    r.y = fmaf(a.y, s, bb.y);
    r.z = fmaf(a.z, s, bb.z);
    r.w = fmaf(a.w, s, bb.w);
    if (RELU) {
        r.x = fmaxf(r.x, 0.f); r.y = fmaxf(r.y, 0.f);
        r.z = fmaxf(r.z, 0.f); r.w = fmaxf(r.w, 0.f);
    }
    ((float4*)out)[idx] = r;
}

// ---------------- launch ----------------
extern "C" void kernel_launch(void* const* d_in, const int* in_sizes, int n_in,
                              void* d_out, int out_size) {
    const float* feat = (const float*)d_in[0];
    const float* W1   = (const float*)d_in[1];
    const float* b1   = (const float*)d_in[2];
    const float* W2   = (const float*)d_in[3];
    const float* b2   = (const float*)d_in[4];
    const float* W3   = (const float*)d_in[5];
    const float* b3   = (const float*)d_in[6];
    const int*   src  = (const int*)d_in[7];
    const int*   dst  = (const int*)d_in[8];

    const int N  = in_sizes[0] / 128;
    const int nE = in_sizes[7];
    float* out = (float*)d_out;

    float *P = nullptr, *H = nullptr;
    cudaGetSymbolAddress((void**)&P, g_P);
    cudaGetSymbolAddress((void**)&H, g_H);

    const int SMEM128 = (128 * 128 + 64 * 132) * 4;  // 99328 B
    const int SMEM64  = (128 * 64  + 64 * 132) * 4;  // 66560 B
    cudaFuncSetAttribute(k_gemm<128,128>, cudaFuncAttributeMaxDynamicSharedMemorySize, SMEM128);
    cudaFuncSetAttribute(k_gemm<64,40>,   cudaFuncAttributeMaxDynamicSharedMemorySize, SMEM64);

    const int T = 256;
    const int gemmBlocks = (N + 63) / 64;
    const int nDeg4   = (N + 3) / 4;
    const int nAgg128 = N * 32;  // float4 count for [N,128]
    const int nAgg40  = N * 10;  // float4 count for [N,40]

    // degrees + norms
    k_zero_deg<<<(nDeg4 + T - 1) / T, T>>>(nDeg4);
    k_degree<<<(nE + T - 1) / T, T>>>(src, dst, nE);
    k_norm<<<(N + T - 1) / T, T>>>(N);

    // ---- layer 1 ----
    k_gemm<128,128><<<gemmBlocks, T, SMEM128>>>(feat, W1, P, N);
    k_zero_agg<<<(nAgg128 + T - 1) / T, T>>>(nAgg128);
    k_agg128<<<(nE * 32 + T - 1) / T, T>>>(src, dst, nE);
    k_epilogue<true, 32><<<(nAgg128 + T - 1) / T, T>>>(b1, H, N);

    // ---- layer 2 ----
    k_gemm<128,128><<<gemmBlocks, T, SMEM128>>>(H, W2, P, N);
    k_zero_agg<<<(nAgg128 + T - 1) / T, T>>>(nAgg128);
    k_agg128<<<(nE * 32 + T - 1) / T, T>>>(src, dst, nE);
    k_epilogue<true, 32><<<(nAgg128 + T - 1) / T, T>>>(b2, H, N);

    // ---- layer 3 ----
    k_gemm<64,40><<<gemmBlocks, T, SMEM64>>>(H, W3, P, N);
    k_zero_agg<<<(nAgg40 + T - 1) / T, T>>>(nAgg40);
    k_agg40<<<(nE * 10 + T - 1) / T, T>>>(src, dst, nE);
    k_epilogue<false, 10><<<(nAgg40 + T - 1) / T, T>>>(b3, out, N);
}

// round 2
// speedup vs baseline: 1.5222x; 1.5222x over previous
#include <cuda_runtime.h>
#include <cstdint>

#define NMAX 50000
#define NEMAX 1000000

// ---------------- scratch ----------------
__device__ __align__(16) float g_P  [(size_t)NMAX * 128];
__device__ __align__(16) float g_H  [(size_t)NMAX * 128];
__device__ __align__(16) int   g_outdeg[NMAX + 8];
__device__ __align__(16) int   g_indeg [NMAX + 8];
__device__ __align__(16) float g_onorm [NMAX + 8];
__device__ __align__(16) float g_inorm [NMAX + 8];
__device__ int g_esrc[NEMAX];
__device__ int g_rowstart[NMAX + 8];
__device__ int g_cursor[NMAX + 8];
__device__ int g_scan[NMAX + 8];
__device__ int g_bsum[512];

// ---------------- degrees / norms ----------------
__global__ void k_zero_deg(int n4) {
    int i = blockIdx.x * blockDim.x + threadIdx.x;
    if (i < n4) {
        ((int4*)g_outdeg)[i] = make_int4(0, 0, 0, 0);
        ((int4*)g_indeg)[i]  = make_int4(0, 0, 0, 0);
    }
}

__global__ void k_degree(const int* __restrict__ src, const int* __restrict__ dst, int nE) {
    int i = blockIdx.x * blockDim.x + threadIdx.x;
    if (i < nE) {
        atomicAdd(&g_outdeg[src[i]], 1);
        atomicAdd(&g_indeg[dst[i]], 1);
    }
}

__global__ void k_norm(int n) {
    int i = blockIdx.x * blockDim.x + threadIdx.x;
    if (i < n) {
        g_onorm[i] = rsqrtf(fmaxf((float)g_outdeg[i], 1.f));
        g_inorm[i] = rsqrtf(fmaxf((float)g_indeg[i], 1.f));
    }
}

// ---------------- prefix sum over in_deg -> rowstart ----------------
__global__ void k_scan1(int n) {
    __shared__ int sm[256];
    int tid = threadIdx.x;
    int i = blockIdx.x * 256 + tid;
    int v = (i < n) ? g_indeg[i] : 0;
    sm[tid] = v;
    __syncthreads();
    for (int off = 1; off < 256; off <<= 1) {
        int t = 0;
        if (tid >= off) t = sm[tid - off];
        __syncthreads();
        if (tid >= off) sm[tid] += t;
        __syncthreads();
    }
    if (i < n) g_scan[i] = sm[tid];
    if (tid == 255) g_bsum[blockIdx.x] = sm[255];
}

__global__ void k_scan2(int nb) {
    __shared__ int sm[256];
    int tid = threadIdx.x;
    int v = (tid < nb) ? g_bsum[tid] : 0;
    sm[tid] = v;
    __syncthreads();
    for (int off = 1; off < 256; off <<= 1) {
        int t = 0;
        if (tid >= off) t = sm[tid - off];
        __syncthreads();
        if (tid >= off) sm[tid] += t;
        __syncthreads();
    }
    if (tid < nb) g_bsum[tid] = sm[tid] - v;   // exclusive
}

__global__ void k_scan3(int n) {
    int i = blockIdx.x * blockDim.x + threadIdx.x;
    if (i < n) {
        int incl = g_scan[i] + g_bsum[i >> 8];
        int start = incl - g_indeg[i];
        g_rowstart[i] = start;
        g_cursor[i]   = start;
        if (i == n - 1) g_rowstart[n] = incl;
    }
}

__global__ void k_scatter(const int* __restrict__ src, const int* __restrict__ dst, int nE) {
    int i = blockIdx.x * blockDim.x + threadIdx.x;
    if (i < nE) {
        int d = dst[i];
        int pos = atomicAdd(&g_cursor[d], 1);
        g_esrc[pos] = src[i];
    }
}

// ---------------- GEMM 128x128: P[r,:] = (X[r,:]*onorm[r]) @ W ----------------
// Tile 128 rows x 128 cols, 256 threads, 8x8 per thread. W staged in 2 K-halves.
__global__ void __launch_bounds__(256)
k_gemm128_v2(const float* __restrict__ X, const float* __restrict__ W,
             float* __restrict__ P, int n) {
    extern __shared__ float sm[];
    float* Xs = sm;                 // [128][132]
    float* Ws = sm + 128 * 132;     // [64][128]

    const int tid = threadIdx.x;
    const int r0  = blockIdx.x * 128;
    const int tx  = tid & 15;       // col group
    const int ty  = tid >> 4;       // row group

    // stage X tile with onorm fused (float4, conflict-free)
    for (int q = tid; q < 128 * 32; q += 256) {
        int r = q >> 5, c4 = q & 31;
        int gr = r0 + r;
        float4 v = make_float4(0.f, 0.f, 0.f, 0.f);
        if (gr < n) {
            v = ((const float4*)(X + (size_t)gr * 128))[c4];
            float s = g_onorm[gr];
            v.x *= s; v.y *= s; v.z *= s; v.w *= s;
        }
        *((float4*)(Xs + r * 132 + c4 * 4)) = v;
    }

    float acc[8][8];
#pragma unroll
    for (int i = 0; i < 8; ++i)
#pragma unroll
        for (int j = 0; j < 8; ++j) acc[i][j] = 0.f;

    const float* xb = Xs + ty * 8 * 132;

    for (int half = 0; half < 2; ++half) {
        __syncthreads();
        // stage W half: rows [half*64, half*64+64)
        for (int q = tid; q < 64 * 32; q += 256)
            ((float4*)Ws)[q] = ((const float4*)W)[half * 2048 + q];
        __syncthreads();

        const float* xh = xb + half * 64;
#pragma unroll 4
        for (int kk = 0; kk < 64; ++kk) {
            float4 b0 = ((const float4*)Ws)[kk * 32 + tx];       // cols tx*4..+4
            float4 b1 = ((const float4*)Ws)[kk * 32 + 16 + tx];  // cols 64+tx*4..+4
            float a[8];
#pragma unroll
            for (int i = 0; i < 8; ++i) a[i] = xh[i * 132 + kk];
#pragma unroll
            for (int i = 0; i < 8; ++i) {
                acc[i][0] = fmaf(a[i], b0.x, acc[i][0]);
                acc[i][1] = fmaf(a[i], b0.y, acc[i][1]);
                acc[i][2] = fmaf(a[i], b0.z, acc[i][2]);
                acc[i][3] = fmaf(a[i], b0.w, acc[i][3]);
                acc[i][4] = fmaf(a[i], b1.x, acc[i][4]);
                acc[i][5] = fmaf(a[i], b1.y, acc[i][5]);
                acc[i][6] = fmaf(a[i], b1.z, acc[i][6]);
                acc[i][7] = fmaf(a[i], b1.w, acc[i][7]);
            }
        }
    }

#pragma unroll
    for (int i = 0; i < 8; ++i) {
        int gr = r0 + ty * 8 + i;
        if (gr >= n) continue;
        float4* prow = (float4*)(P + (size_t)gr * 128);
        prow[tx]      = make_float4(acc[i][0], acc[i][1], acc[i][2], acc[i][3]);
        prow[16 + tx] = make_float4(acc[i][4], acc[i][5], acc[i][6], acc[i][7]);
    }
}

// ---------------- GEMM for layer 3 (128 -> 40), 64-row tiles ----------------
template<int COLS, int NCOUT>
__global__ void __launch_bounds__(256)
k_gemm(const float* __restrict__ X, const float* __restrict__ W,
       float* __restrict__ P, int n) {
    extern __shared__ float sm[];
    float* Ws = sm;
    float* Xs = sm + 128 * COLS;

    const int tid = threadIdx.x;
    const int r0  = blockIdx.x * 64;

    for (int q = tid; q < 128 * COLS; q += 256) {
        int k = q / COLS, c = q % COLS;
        Ws[q] = (c < NCOUT) ? W[k * NCOUT + c] : 0.f;
    }
    for (int q = tid; q < 64 * 32; q += 256) {
        int r = q >> 5, c4 = q & 31;
        int gr = r0 + r;
        float4 v = make_float4(0.f, 0.f, 0.f, 0.f);
        if (gr < n) {
            v = ((const float4*)(X + (size_t)gr * 128))[c4];
            float s = g_onorm[gr];
            v.x *= s; v.y *= s; v.z *= s; v.w *= s;
        }
        *((float4*)(Xs + r * 132 + c4 * 4)) = v;
    }
    __syncthreads();

    constexpr int CG  = COLS / 4;
    constexpr int RGC = 256 / CG;
    constexpr int RPT = 64 / RGC;
    const int cg = tid % CG;
    const int rg = tid / CG;

    float acc[RPT][4];
#pragma unroll
    for (int i = 0; i < RPT; ++i)
#pragma unroll
        for (int j = 0; j < 4; ++j) acc[i][j] = 0.f;

    const float* xbase = Xs + rg * RPT * 132;
    const float4* wc = ((const float4*)Ws) + cg;
#pragma unroll 4
    for (int k = 0; k < 128; ++k) {
        float4 b = wc[k * CG];
#pragma unroll
        for (int i = 0; i < RPT; ++i) {
            float a = xbase[i * 132 + k];
            acc[i][0] = fmaf(a, b.x, acc[i][0]);
            acc[i][1] = fmaf(a, b.y, acc[i][1]);
            acc[i][2] = fmaf(a, b.z, acc[i][2]);
            acc[i][3] = fmaf(a, b.w, acc[i][3]);
        }
    }

#pragma unroll
    for (int i = 0; i < RPT; ++i) {
        int gr = r0 + rg * RPT + i;
        if (gr >= n) continue;
        int c = cg * 4;
#pragma unroll
        for (int j = 0; j < 4; ++j)
            if (c + j < NCOUT) P[(size_t)gr * NCOUT + c + j] = acc[i][j];
    }
}

// ---------------- CSR aggregation (gather), fused epilogue ----------------
// One warp per dst node, 128 dims: lane owns one float4.
template<bool RELU>
__global__ void __launch_bounds__(256)
k_csr_agg128(const float* __restrict__ b, float* __restrict__ out, int n) {
    int w    = (blockIdx.x * blockDim.x + threadIdx.x) >> 5;
    int lane = threadIdx.x & 31;
    if (w >= n) return;

    int beg = g_rowstart[w];
    int end = g_rowstart[w + 1];

    float4 acc = make_float4(0.f, 0.f, 0.f, 0.f);
    const float4* P4 = (const float4*)g_P;

    for (int base = beg; base < end; base += 32) {
        int cnt = min(32, end - base);
        int myidx = (lane < cnt) ? g_esrc[base + lane] : 0;
        int j = 0;
        for (; j + 4 <= cnt; j += 4) {
            int s0 = __shfl_sync(0xffffffffu, myidx, j);
            int s1 = __shfl_sync(0xffffffffu, myidx, j + 1);
            int s2 = __shfl_sync(0xffffffffu, myidx, j + 2);
            int s3 = __shfl_sync(0xffffffffu, myidx, j + 3);
            float4 v0 = P4[(size_t)s0 * 32 + lane];
            float4 v1 = P4[(size_t)s1 * 32 + lane];
            float4 v2 = P4[(size_t)s2 * 32 + lane];
            float4 v3 = P4[(size_t)s3 * 32 + lane];
            acc.x += v0.x; acc.y += v0.y; acc.z += v0.z; acc.w += v0.w;
            acc.x += v1.x; acc.y += v1.y; acc.z += v1.z; acc.w += v1.w;
            acc.x += v2.x; acc.y += v2.y; acc.z += v2.z; acc.w += v2.w;
            acc.x += v3.x; acc.y += v3.y; acc.z += v3.z; acc.w += v3.w;
        }
        for (; j < cnt; ++j) {
            int s = __shfl_sync(0xffffffffu, myidx, j);
            float4 v = P4[(size_t)s * 32 + lane];
            acc.x += v.x; acc.y += v.y; acc.z += v.z; acc.w += v.w;
        }
    }

    float sc  = g_inorm[w];
    float4 bb = ((const float4*)b)[lane];
    float4 r;
    r.x = fmaf(acc.x, sc, bb.x);
    r.y = fmaf(acc.y, sc, bb.y);
    r.z = fmaf(acc.z, sc, bb.z);
    r.w = fmaf(acc.w, sc, bb.w);
    if (RELU) {
        r.x = fmaxf(r.x, 0.f); r.y = fmaxf(r.y, 0.f);
        r.z = fmaxf(r.z, 0.f); r.w = fmaxf(r.w, 0.f);
    }
    ((float4*)(out + (size_t)w * 128))[lane] = r;
}

// 40 dims: thread per (node, float4-group). g is 0..9.
__global__ void __launch_bounds__(256)
k_csr_agg40(const float* __restrict__ b, float* __restrict__ out, int n) {
    int t = blockIdx.x * blockDim.x + threadIdx.x;
    if (t >= n * 10) return;
    int node = t / 10;
    int g    = t - node * 10;

    int beg = g_rowstart[node];
    int end = g_rowstart[node + 1];

    float4 acc = make_float4(0.f, 0.f, 0.f, 0.f);
    const float4* P4 = (const float4*)g_P;
    int e = beg;
    for (; e + 2 <= end; e += 2) {
        int s0 = g_esrc[e];
        int s1 = g_esrc[e + 1];
        float4 v0 = P4[(size_t)s0 * 10 + g];
        float4 v1 = P4[(size_t)s1 * 10 + g];
        acc.x += v0.x; acc.y += v0.y; acc.z += v0.z; acc.w += v0.w;
        acc.x += v1.x; acc.y += v1.y; acc.z += v1.z; acc.w += v1.w;
    }
    if (e < end) {
        int s = g_esrc[e];
        float4 v = P4[(size_t)s * 10 + g];
        acc.x += v.x; acc.y += v.y; acc.z += v.z; acc.w += v.w;
    }

    float sc  = g_inorm[node];
    float4 bb = ((const float4*)b)[g];
    float4 r;
    r.x = fmaf(acc.x, sc, bb.x);
    r.y = fmaf(acc.y, sc, bb.y);
    r.z = fmaf(acc.z, sc, bb.z);
    r.w = fmaf(acc.w, sc, bb.w);
    ((float4*)(out + (size_t)node * 40))[g] = r;
}

// ---------------- launch ----------------
extern "C" void kernel_launch(void* const* d_in, const int* in_sizes, int n_in,
                              void* d_out, int out_size) {
    const float* feat = (const float*)d_in[0];
    const float* W1   = (const float*)d_in[1];
    const float* b1   = (const float*)d_in[2];
    const float* W2   = (const float*)d_in[3];
    const float* b2   = (const float*)d_in[4];
    const float* W3   = (const float*)d_in[5];
    const float* b3   = (const float*)d_in[6];
    const int*   src  = (const int*)d_in[7];
    const int*   dst  = (const int*)d_in[8];

    const int N  = in_sizes[0] / 128;
    const int nE = in_sizes[7];
    float* out = (float*)d_out;

    float *P = nullptr, *H = nullptr;
    cudaGetSymbolAddress((void**)&P, g_P);
    cudaGetSymbolAddress((void**)&H, g_H);

    const int SMEMV2 = (128 * 132 + 64 * 128) * 4;   // 100352 B
    const int SMEM64 = (128 * 64 + 64 * 132) * 4;    // 66560 B
    cudaFuncSetAttribute(k_gemm128_v2, cudaFuncAttributeMaxDynamicSharedMemorySize, SMEMV2);
    cudaFuncSetAttribute(k_gemm<64, 40>, cudaFuncAttributeMaxDynamicSharedMemorySize, SMEM64);

    const int T = 256;
    const int gemmV2Blocks = (N + 127) / 128;
    const int gemm3Blocks  = (N + 63) / 64;
    const int nDeg4 = (N + 3) / 4;
    const int scanBlocks = (N + 255) / 256;

    // degrees, norms, CSR build
    k_zero_deg<<<(nDeg4 + T - 1) / T, T>>>(nDeg4);
    k_degree<<<(nE + T - 1) / T, T>>>(src, dst, nE);
    k_norm<<<(N + T - 1) / T, T>>>(N);
    k_scan1<<<scanBlocks, 256>>>(N);
    k_scan2<<<1, 256>>>(scanBlocks);
    k_scan3<<<scanBlocks, 256>>>(N);
    k_scatter<<<(nE + T - 1) / T, T>>>(src, dst, nE);

    // layer 1
    k_gemm128_v2<<<gemmV2Blocks, T, SMEMV2>>>(feat, W1, P, N);
    k_csr_agg128<true><<<(N * 32 + T - 1) / T, T>>>(b1, H, N);

    // layer 2
    k_gemm128_v2<<<gemmV2Blocks, T, SMEMV2>>>(H, W2, P, N);
    k_csr_agg128<true><<<(N * 32 + T - 1) / T, T>>>(b2, H, N);

    // layer 3
    k_gemm<64, 40><<<gemm3Blocks, T, SMEM64>>>(H, W3, P, N);
    k_csr_agg40<<<(N * 10 + T - 1) / T, T>>>(b3, out, N);
}

// round 4
// speedup vs baseline: 1.8229x; 1.1976x over previous
#include <cuda_runtime.h>
#include <cstdint>

#define NMAX 50000
#define NEMAX 1000000

// ---------------- scratch ----------------
__device__ __align__(16) float g_P  [(size_t)NMAX * 128];
__device__ __align__(16) float g_H  [(size_t)NMAX * 128];
__device__ __align__(16) int   g_outdeg[NMAX + 8];
__device__ __align__(16) int   g_indeg [NMAX + 8];
__device__ __align__(16) float g_onorm [NMAX + 8];
__device__ __align__(16) float g_inorm [NMAX + 8];
__device__ int g_esrc[NEMAX];
__device__ int g_rowstart[NMAX + 8];
__device__ int g_cursor[NMAX + 8];
__device__ int g_scan[NMAX + 8];
__device__ int g_bsum[512];

// ---------------- packed f32x2 helpers ----------------
__device__ __forceinline__ uint32_t smem_u32(const void* p) {
    uint32_t a;
    asm("{ .reg .u64 t; cvta.to.shared.u64 t, %1; cvt.u32.u64 %0, t; }" : "=r"(a) : "l"(p));
    return a;
}
__device__ __forceinline__ unsigned long long lds_b64(uint32_t a) {
    unsigned long long v;
    asm volatile("ld.shared.b64 %0, [%1];" : "=l"(v) : "r"(a));
    return v;
}
__device__ __forceinline__ uint32_t lds_b32(uint32_t a) {
    uint32_t v;
    asm volatile("ld.shared.b32 %0, [%1];" : "=r"(v) : "r"(a));
    return v;
}
__device__ __forceinline__ unsigned long long dup2(uint32_t x) {
    unsigned long long v;
    asm("mov.b64 %0, {%1, %1};" : "=l"(v) : "r"(x));
    return v;
}
__device__ __forceinline__ void fma2(unsigned long long& d, unsigned long long a, unsigned long long b) {
    asm("fma.rn.f32x2 %0, %1, %2, %0;" : "+l"(d) : "l"(a), "l"(b));
}

// ---------------- degrees / norms ----------------
__global__ void k_degree(const int* __restrict__ src, const int* __restrict__ dst, int nE) {
    int i = blockIdx.x * blockDim.x + threadIdx.x;
    if (i < nE) {
        atomicAdd(&g_outdeg[src[i]], 1);
        atomicAdd(&g_indeg[dst[i]], 1);
    }
}
__global__ void k_norm(int n) {
    int i = blockIdx.x * blockDim.x + threadIdx.x;
    if (i < n) {
        g_onorm[i] = rsqrtf(fmaxf((float)g_outdeg[i], 1.f));
        g_inorm[i] = rsqrtf(fmaxf((float)g_indeg[i], 1.f));
    }
}

// ---------------- prefix sum -> rowstart / cursor ----------------
__global__ void k_scan1(int n) {
    __shared__ int sm[256];
    int tid = threadIdx.x;
    int i = blockIdx.x * 256 + tid;
    int v = (i < n) ? g_indeg[i] : 0;
    sm[tid] = v;
    __syncthreads();
    for (int off = 1; off < 256; off <<= 1) {
        int t = 0;
        if (tid >= off) t = sm[tid - off];
        __syncthreads();
        if (tid >= off) sm[tid] += t;
        __syncthreads();
    }
    if (i < n) g_scan[i] = sm[tid];
    if (tid == 255) g_bsum[blockIdx.x] = sm[255];
}
__global__ void k_scan2(int nb) {
    __shared__ int sm[256];
    int tid = threadIdx.x;
    int v = (tid < nb) ? g_bsum[tid] : 0;
    sm[tid] = v;
    __syncthreads();
    for (int off = 1; off < 256; off <<= 1) {
        int t = 0;
        if (tid >= off) t = sm[tid - off];
        __syncthreads();
        if (tid >= off) sm[tid] += t;
        __syncthreads();
    }
    if (tid < nb) g_bsum[tid] = sm[tid] - v;
}
__global__ void k_scan3(int n) {
    int i = blockIdx.x * blockDim.x + threadIdx.x;
    if (i < n) {
        int incl = g_scan[i] + g_bsum[i >> 8];
        int start = incl - g_indeg[i];
        g_rowstart[i] = start;
        g_cursor[i]   = start;
        if (i == n - 1) g_rowstart[n] = incl;
    }
}
__global__ void k_scatter(const int* __restrict__ src, const int* __restrict__ dst, int nE) {
    int i = blockIdx.x * blockDim.x + threadIdx.x;
    if (i < nE) {
        int d = dst[i];
        int pos = atomicAdd(&g_cursor[d], 1);
        g_esrc[pos] = src[i];
    }
}

// ---------------- GEMM 128x128 with packed f32x2 FMA ----------------
// Tile 128 rows x 128 cols, 256 threads, 8x8 per thread (accs packed in pairs).
__global__ void __launch_bounds__(256)
k_gemm128_v3(const float* __restrict__ X, const float* __restrict__ W,
             float* __restrict__ P, int n) {
    extern __shared__ float sm[];
    float* Xs = sm;                 // [128][132]
    float* Ws = sm + 128 * 132;     // [64][128] (one K-half at a time)

    const uint32_t smem_base = smem_u32(sm);
    const uint32_t WS_OFF = 128 * 132 * 4;   // 67584 bytes

    const int tid = threadIdx.x;
    const int r0  = blockIdx.x * 128;
    const int tx  = tid & 15;       // col group: cols [4tx,4tx+4) and [64+4tx, 64+4tx+4)
    const int ty  = tid >> 4;       // row group: rows [8ty, 8ty+8)

    // stage X tile with onorm fused
    for (int q = tid; q < 128 * 32; q += 256) {
        int r = q >> 5, c4 = q & 31;
        int gr = r0 + r;
        float4 v = make_float4(0.f, 0.f, 0.f, 0.f);
        if (gr < n) {
            v = ((const float4*)(X + (size_t)gr * 128))[c4];
            float s = g_onorm[gr];
            v.x *= s; v.y *= s; v.z *= s; v.w *= s;
        }
        *((float4*)(Xs + r * 132 + c4 * 4)) = v;
    }

    unsigned long long acc[8][4];
#pragma unroll
    for (int i = 0; i < 8; ++i)
#pragma unroll
        for (int j = 0; j < 4; ++j) acc[i][j] = 0ull;

    const uint32_t xrow0 = smem_base + (uint32_t)(ty * 8 * 132) * 4;
    const uint32_t wbase = smem_base + WS_OFF + (uint32_t)tx * 16;

    for (int half = 0; half < 2; ++half) {
        __syncthreads();
        for (int q = tid; q < 64 * 32; q += 256)
            ((float4*)Ws)[q] = ((const float4*)W)[half * 2048 + q];
        __syncthreads();

        const uint32_t xh = xrow0 + (uint32_t)(half * 64) * 4;
#pragma unroll 2
        for (int kk = 0; kk < 64; ++kk) {
            uint32_t wb = wbase + (uint32_t)kk * 512;
            unsigned long long b0 = lds_b64(wb);
            unsigned long long b1 = lds_b64(wb + 8);
            unsigned long long b2 = lds_b64(wb + 256);
            unsigned long long b3 = lds_b64(wb + 264);
#pragma unroll
            for (int i = 0; i < 8; ++i) {
                unsigned long long ap = dup2(lds_b32(xh + (uint32_t)(i * 132 + kk) * 4));
                fma2(acc[i][0], ap, b0);
                fma2(acc[i][1], ap, b1);
                fma2(acc[i][2], ap, b2);
                fma2(acc[i][3], ap, b3);
            }
        }
    }

#pragma unroll
    for (int i = 0; i < 8; ++i) {
        int gr = r0 + ty * 8 + i;
        if (gr >= n) continue;
        float4* prow = (float4*)(P + (size_t)gr * 128);
        float2 p0 = *(float2*)&acc[i][0];
        float2 p1 = *(float2*)&acc[i][1];
        float2 p2 = *(float2*)&acc[i][2];
        float2 p3 = *(float2*)&acc[i][3];
        prow[tx]      = make_float4(p0.x, p0.y, p1.x, p1.y);
        prow[16 + tx] = make_float4(p2.x, p2.y, p3.x, p3.y);
    }
}

// ---------------- GEMM for layer 3 (128 -> 40) ----------------
template<int COLS, int NCOUT>
__global__ void __launch_bounds__(256)
k_gemm(const float* __restrict__ X, const float* __restrict__ W,
       float* __restrict__ P, int n) {
    extern __shared__ float sm[];
    float* Ws = sm;
    float* Xs = sm + 128 * COLS;

    const int tid = threadIdx.x;
    const int r0  = blockIdx.x * 64;

    for (int q = tid; q < 128 * COLS; q += 256) {
        int k = q / COLS, c = q % COLS;
        Ws[q] = (c < NCOUT) ? W[k * NCOUT + c] : 0.f;
    }
    for (int q = tid; q < 64 * 32; q += 256) {
        int r = q >> 5, c4 = q & 31;
        int gr = r0 + r;
        float4 v = make_float4(0.f, 0.f, 0.f, 0.f);
        if (gr < n) {
            v = ((const float4*)(X + (size_t)gr * 128))[c4];
            float s = g_onorm[gr];
            v.x *= s; v.y *= s; v.z *= s; v.w *= s;
        }
        *((float4*)(Xs + r * 132 + c4 * 4)) = v;
    }
    __syncthreads();

    constexpr int CG  = COLS / 4;
    constexpr int RGC = 256 / CG;
    constexpr int RPT = 64 / RGC;
    const int cg = tid % CG;
    const int rg = tid / CG;

    float acc[RPT][4];
#pragma unroll
    for (int i = 0; i < RPT; ++i)
#pragma unroll
        for (int j = 0; j < 4; ++j) acc[i][j] = 0.f;

    const float* xbase = Xs + rg * RPT * 132;
    const float4* wc = ((const float4*)Ws) + cg;
#pragma unroll 4
    for (int k = 0; k < 128; ++k) {
        float4 b = wc[k * CG];
#pragma unroll
        for (int i = 0; i < RPT; ++i) {
            float a = xbase[i * 132 + k];
            acc[i][0] = fmaf(a, b.x, acc[i][0]);
            acc[i][1] = fmaf(a, b.y, acc[i][1]);
            acc[i][2] = fmaf(a, b.z, acc[i][2]);
            acc[i][3] = fmaf(a, b.w, acc[i][3]);
        }
    }

#pragma unroll
    for (int i = 0; i < RPT; ++i) {
        int gr = r0 + rg * RPT + i;
        if (gr >= n) continue;
        int c = cg * 4;
#pragma unroll
        for (int j = 0; j < 4; ++j)
            if (c + j < NCOUT) P[(size_t)gr * NCOUT + c + j] = acc[i][j];
    }
}

// ---------------- CSR aggregation (gather), fused epilogue ----------------
template<bool RELU>
__global__ void __launch_bounds__(256)
k_csr_agg128(const float* __restrict__ b, float* __restrict__ out, int n) {
    int w    = (blockIdx.x * blockDim.x + threadIdx.x) >> 5;
    int lane = threadIdx.x & 31;
    if (w >= n) return;

    int beg = g_rowstart[w];
    int end = g_rowstart[w + 1];

    float4 acc = make_float4(0.f, 0.f, 0.f, 0.f);
    const float4* P4 = (const float4*)g_P;

    for (int base = beg; base < end; base += 32) {
        int cnt = min(32, end - base);
        int myidx = (lane < cnt) ? g_esrc[base + lane] : 0;
        int j = 0;
        for (; j + 4 <= cnt; j += 4) {
            int s0 = __shfl_sync(0xffffffffu, myidx, j);
            int s1 = __shfl_sync(0xffffffffu, myidx, j + 1);
            int s2 = __shfl_sync(0xffffffffu, myidx, j + 2);
            int s3 = __shfl_sync(0xffffffffu, myidx, j + 3);
            float4 v0 = P4[(size_t)s0 * 32 + lane];
            float4 v1 = P4[(size_t)s1 * 32 + lane];
            float4 v2 = P4[(size_t)s2 * 32 + lane];
            float4 v3 = P4[(size_t)s3 * 32 + lane];
            acc.x += v0.x; acc.y += v0.y; acc.z += v0.z; acc.w += v0.w;
            acc.x += v1.x; acc.y += v1.y; acc.z += v1.z; acc.w += v1.w;
            acc.x += v2.x; acc.y += v2.y; acc.z += v2.z; acc.w += v2.w;
            acc.x += v3.x; acc.y += v3.y; acc.z += v3.z; acc.w += v3.w;
        }
        for (; j < cnt; ++j) {
            int s = __shfl_sync(0xffffffffu, myidx, j);
            float4 v = P4[(size_t)s * 32 + lane];
            acc.x += v.x; acc.y += v.y; acc.z += v.z; acc.w += v.w;
        }
    }

    float sc  = g_inorm[w];
    float4 bb = ((const float4*)b)[lane];
    float4 r;
    r.x = fmaf(acc.x, sc, bb.x);
    r.y = fmaf(acc.y, sc, bb.y);
    r.z = fmaf(acc.z, sc, bb.z);
    r.w = fmaf(acc.w, sc, bb.w);
    if (RELU) {
        r.x = fmaxf(r.x, 0.f); r.y = fmaxf(r.y, 0.f);
        r.z = fmaxf(r.z, 0.f); r.w = fmaxf(r.w, 0.f);
    }
    ((float4*)(out + (size_t)w * 128))[lane] = r;
}

__global__ void __launch_bounds__(256)
k_csr_agg40(const float* __restrict__ b, float* __restrict__ out, int n) {
    int t = blockIdx.x * blockDim.x + threadIdx.x;
    if (t >= n * 10) return;
    int node = t / 10;
    int g    = t - node * 10;

    int beg = g_rowstart[node];
    int end = g_rowstart[node + 1];

    float4 acc = make_float4(0.f, 0.f, 0.f, 0.f);
    const float4* P4 = (const float4*)g_P;
    int e = beg;
    for (; e + 2 <= end; e += 2) {
        int s0 = g_esrc[e];
        int s1 = g_esrc[e + 1];
        float4 v0 = P4[(size_t)s0 * 10 + g];
        float4 v1 = P4[(size_t)s1 * 10 + g];
        acc.x += v0.x; acc.y += v0.y; acc.z += v0.z; acc.w += v0.w;
        acc.x += v1.x; acc.y += v1.y; acc.z += v1.z; acc.w += v1.w;
    }
    if (e < end) {
        int s = g_esrc[e];
        float4 v = P4[(size_t)s * 10 + g];
        acc.x += v.x; acc.y += v.y; acc.z += v.z; acc.w += v.w;
    }

    float sc  = g_inorm[node];
    float4 bb = ((const float4*)b)[g];
    float4 r;
    r.x = fmaf(acc.x, sc, bb.x);
    r.y = fmaf(acc.y, sc, bb.y);
    r.z = fmaf(acc.z, sc, bb.z);
    r.w = fmaf(acc.w, sc, bb.w);
    ((float4*)(out + (size_t)node * 40))[g] = r;
}

// ---------------- launch ----------------
extern "C" void kernel_launch(void* const* d_in, const int* in_sizes, int n_in,
                              void* d_out, int out_size) {
    const float* feat = (const float*)d_in[0];
    const float* W1   = (const float*)d_in[1];
    const float* b1   = (const float*)d_in[2];
    const float* W2   = (const float*)d_in[3];
    const float* b2   = (const float*)d_in[4];
    const float* W3   = (const float*)d_in[5];
    const float* b3   = (const float*)d_in[6];
    const int*   src  = (const int*)d_in[7];
    const int*   dst  = (const int*)d_in[8];

    const int N  = in_sizes[0] / 128;
    const int nE = in_sizes[7];
    float* out = (float*)d_out;

    float *P = nullptr, *H = nullptr;
    void *odeg = nullptr, *ideg = nullptr;
    cudaGetSymbolAddress((void**)&P, g_P);
    cudaGetSymbolAddress((void**)&H, g_H);
    cudaGetSymbolAddress(&odeg, g_outdeg);
    cudaGetSymbolAddress(&ideg, g_indeg);

    const int SMEMV3 = (128 * 132 + 64 * 128) * 4;   // 100352 B
    const int SMEM64 = (128 * 64 + 64 * 132) * 4;    // 66560 B
    cudaFuncSetAttribute(k_gemm128_v3, cudaFuncAttributeMaxDynamicSharedMemorySize, SMEMV3);
    cudaFuncSetAttribute(k_gemm<64, 40>, cudaFuncAttributeMaxDynamicSharedMemorySize, SMEM64);

    const int T = 256;
    const int gemmBlocks  = (N + 127) / 128;
    const int gemm3Blocks = (N + 63) / 64;
    const int scanBlocks  = (N + 255) / 256;

    // side stream + events for fork/join (host objects only; no device alloc)
    cudaStream_t s1;
    cudaStreamCreateWithFlags(&s1, cudaStreamNonBlocking);
    cudaEvent_t e1, e2;
    cudaEventCreateWithFlags(&e1, cudaEventDisableTiming);
    cudaEventCreateWithFlags(&e2, cudaEventDisableTiming);

    // --- main stream: degrees + norms (GEMM1 needs onorm) ---
    cudaMemsetAsync(odeg, 0, (size_t)N * 4, 0);
    cudaMemsetAsync(ideg, 0, (size_t)N * 4, 0);
    k_degree<<<(nE + T - 1) / T, T>>>(src, dst, nE);
    k_norm<<<(N + T - 1) / T, T>>>(N);

    // --- fork: CSR build on s1, GEMM1 on main ---
    cudaEventRecord(e1, 0);
    cudaStreamWaitEvent(s1, e1, 0);
    k_scan1<<<scanBlocks, 256, 0, s1>>>(N);
    k_scan2<<<1, 256, 0, s1>>>(scanBlocks);
    k_scan3<<<scanBlocks, 256, 0, s1>>>(N);
    k_scatter<<<(nE + T - 1) / T, T, 0, s1>>>(src, dst, nE);
    cudaEventRecord(e2, s1);

    k_gemm128_v3<<<gemmBlocks, T, SMEMV3>>>(feat, W1, P, N);

    // --- join ---
    cudaStreamWaitEvent(0, e2, 0);

    // layer 1 aggregation
    k_csr_agg128<true><<<(N * 32 + T - 1) / T, T>>>(b1, H, N);

    // layer 2
    k_gemm128_v3<<<gemmBlocks, T, SMEMV3>>>(H, W2, P, N);
    k_csr_agg128<true><<<(N * 32 + T - 1) / T, T>>>(b2, H, N);

    // layer 3
    k_gemm<64, 40><<<gemm3Blocks, T, SMEM64>>>(H, W3, P, N);
    k_csr_agg40<<<(N * 10 + T - 1) / T, T>>>(b3, out, N);

    // cleanup (skip while capturing to avoid disturbing graph capture)
    cudaStreamCaptureStatus cap = cudaStreamCaptureStatusNone;
    cudaStreamIsCapturing(s1, &cap);
    if (cap == cudaStreamCaptureStatusNone) {
        cudaEventDestroy(e1);
        cudaEventDestroy(e2);
        cudaStreamDestroy(s1);
    }
}

// round 7
// speedup vs baseline: 1.8726x; 1.0272x over previous
#include <cuda_runtime.h>
#include <cuda_fp16.h>
#include <cstdint>

#define NMAX 50000
#define NEMAX 1000000

// ---------------- scratch ----------------
__device__ __align__(16) __half g_P16[(size_t)NMAX * 128];  // fp16 projected features (layers 1,2)
__device__ __align__(16) float g_P  [(size_t)NMAX * 128];   // fp32 projected (layer 3)
__device__ __align__(16) float g_H  [(size_t)NMAX * 128];
__device__ __align__(16) int   g_outdeg[NMAX + 8];
__device__ __align__(16) int   g_indeg [NMAX + 8];
__device__ __align__(16) float g_onorm [NMAX + 8];
__device__ __align__(16) float g_inorm [NMAX + 8];
__device__ int g_esrc[NEMAX];
__device__ int g_rowstart[NMAX + 8];
__device__ int g_cursor[NMAX + 8];
__device__ int g_scan[NMAX + 8];
__device__ int g_bsum[512];

// ---------------- packed f32x2 helpers ----------------
__device__ __forceinline__ uint32_t smem_u32(const void* p) {
    uint32_t a;
    asm("{ .reg .u64 t; cvta.to.shared.u64 t, %1; cvt.u32.u64 %0, t; }" : "=r"(a) : "l"(p));
    return a;
}
__device__ __forceinline__ unsigned long long lds_b64(uint32_t a) {
    unsigned long long v;
    asm volatile("ld.shared.b64 %0, [%1];" : "=l"(v) : "r"(a));
    return v;
}
__device__ __forceinline__ uint32_t lds_b32(uint32_t a) {
    uint32_t v;
    asm volatile("ld.shared.b32 %0, [%1];" : "=r"(v) : "r"(a));
    return v;
}
__device__ __forceinline__ unsigned long long dup2(uint32_t x) {
    unsigned long long v;
    asm("mov.b64 %0, {%1, %1};" : "=l"(v) : "r"(x));
    return v;
}
__device__ __forceinline__ void fma2(unsigned long long& d, unsigned long long a, unsigned long long b) {
    asm("fma.rn.f32x2 %0, %1, %2, %0;" : "+l"(d) : "l"(a), "l"(b));
}

// ---------------- degrees / norms ----------------
__global__ void k_degree(const int* __restrict__ src, const int* __restrict__ dst, int nE) {
    int i = blockIdx.x * blockDim.x + threadIdx.x;
    if (i < nE) {
        atomicAdd(&g_outdeg[src[i]], 1);
        atomicAdd(&g_indeg[dst[i]], 1);
    }
}
__global__ void k_norm(int n) {
    int i = blockIdx.x * blockDim.x + threadIdx.x;
    if (i < n) {
        g_onorm[i] = rsqrtf(fmaxf((float)g_outdeg[i], 1.f));
        g_inorm[i] = rsqrtf(fmaxf((float)g_indeg[i], 1.f));
    }
}

// ---------------- prefix sum -> rowstart / cursor ----------------
__global__ void k_scan1(int n) {
    __shared__ int sm[256];
    int tid = threadIdx.x;
    int i = blockIdx.x * 256 + tid;
    int v = (i < n) ? g_indeg[i] : 0;
    sm[tid] = v;
    __syncthreads();
    for (int off = 1; off < 256; off <<= 1) {
        int t = 0;
        if (tid >= off) t = sm[tid - off];
        __syncthreads();
        if (tid >= off) sm[tid] += t;
        __syncthreads();
    }
    if (i < n) g_scan[i] = sm[tid];
    if (tid == 255) g_bsum[blockIdx.x] = sm[255];
}
__global__ void k_scan2(int nb) {
    __shared__ int sm[256];
    int tid = threadIdx.x;
    int v = (tid < nb) ? g_bsum[tid] : 0;
    sm[tid] = v;
    __syncthreads();
    for (int off = 1; off < 256; off <<= 1) {
        int t = 0;
        if (tid >= off) t = sm[tid - off];
        __syncthreads();
        if (tid >= off) sm[tid] += t;
        __syncthreads();
    }
    if (tid < nb) g_bsum[tid] = sm[tid] - v;
}
__global__ void k_scan3(int n) {
    int i = blockIdx.x * blockDim.x + threadIdx.x;
    if (i < n) {
        int incl = g_scan[i] + g_bsum[i >> 8];
        int start = incl - g_indeg[i];
        g_rowstart[i] = start;
        g_cursor[i]   = start;
        if (i == n - 1) g_rowstart[n] = incl;
    }
}
__global__ void k_scatter(const int* __restrict__ src, const int* __restrict__ dst, int nE) {
    int i = blockIdx.x * blockDim.x + threadIdx.x;
    if (i < nE) {
        int d = dst[i];
        int pos = atomicAdd(&g_cursor[d], 1);
        g_esrc[pos] = src[i];
    }
}

// ---------------- GEMM 128x128 with packed f32x2 FMA, fp16 output ----------------
__global__ void __launch_bounds__(256)
k_gemm128_h(const float* __restrict__ X, const float* __restrict__ W,
            __half* __restrict__ P, int n) {
    extern __shared__ float sm[];
    float* Xs = sm;                 // [128][132]
    float* Ws = sm + 128 * 132;     // [64][128] (one K-half at a time)

    const uint32_t smem_base = smem_u32(sm);
    const uint32_t WS_OFF = 128 * 132 * 4;

    const int tid = threadIdx.x;
    const int r0  = blockIdx.x * 128;
    const int tx  = tid & 15;
    const int ty  = tid >> 4;

    for (int q = tid; q < 128 * 32; q += 256) {
        int r = q >> 5, c4 = q & 31;
        int gr = r0 + r;
        float4 v = make_float4(0.f, 0.f, 0.f, 0.f);
        if (gr < n) {
            v = ((const float4*)(X + (size_t)gr * 128))[c4];
            float s = g_onorm[gr];
            v.x *= s; v.y *= s; v.z *= s; v.w *= s;
        }
        *((float4*)(Xs + r * 132 + c4 * 4)) = v;
    }

    unsigned long long acc[8][4];
#pragma unroll
    for (int i = 0; i < 8; ++i)
#pragma unroll
        for (int j = 0; j < 4; ++j) acc[i][j] = 0ull;

    const uint32_t xrow0 = smem_base + (uint32_t)(ty * 8 * 132) * 4;
    const uint32_t wbase = smem_base + WS_OFF + (uint32_t)tx * 16;

    for (int half = 0; half < 2; ++half) {
        __syncthreads();
        for (int q = tid; q < 64 * 32; q += 256)
            ((float4*)Ws)[q] = ((const float4*)W)[half * 2048 + q];
        __syncthreads();

        const uint32_t xh = xrow0 + (uint32_t)(half * 64) * 4;
#pragma unroll 2
        for (int kk = 0; kk < 64; ++kk) {
            uint32_t wb = wbase + (uint32_t)kk * 512;
            unsigned long long b0 = lds_b64(wb);
            unsigned long long b1 = lds_b64(wb + 8);
            unsigned long long b2 = lds_b64(wb + 256);
            unsigned long long b3 = lds_b64(wb + 264);
#pragma unroll
            for (int i = 0; i < 8; ++i) {
                unsigned long long ap = dup2(lds_b32(xh + (uint32_t)(i * 132 + kk) * 4));
                fma2(acc[i][0], ap, b0);
                fma2(acc[i][1], ap, b1);
                fma2(acc[i][2], ap, b2);
                fma2(acc[i][3], ap, b3);
            }
        }
    }

#pragma unroll
    for (int i = 0; i < 8; ++i) {
        int gr = r0 + ty * 8 + i;
        if (gr >= n) continue;
        __half* prow = P + (size_t)gr * 128;
        float2 p0 = *(float2*)&acc[i][0];
        float2 p1 = *(float2*)&acc[i][1];
        float2 p2 = *(float2*)&acc[i][2];
        float2 p3 = *(float2*)&acc[i][3];
        __half2 h0 = __floats2half2_rn(p0.x, p0.y);
        __half2 h1 = __floats2half2_rn(p1.x, p1.y);
        __half2 h2 = __floats2half2_rn(p2.x, p2.y);
        __half2 h3 = __floats2half2_rn(p3.x, p3.y);
        uint2 w0; w0.x = *(uint32_t*)&h0; w0.y = *(uint32_t*)&h1;
        uint2 w1; w1.x = *(uint32_t*)&h2; w1.y = *(uint32_t*)&h3;
        *(uint2*)(prow + 4 * tx)      = w0;
        *(uint2*)(prow + 64 + 4 * tx) = w1;
    }
}

// ---------------- GEMM for layer 3 (128 -> 40), fp32 ----------------
template<int COLS, int NCOUT>
__global__ void __launch_bounds__(256)
k_gemm(const float* __restrict__ X, const float* __restrict__ W,
       float* __restrict__ P, int n) {
    extern __shared__ float sm[];
    float* Ws = sm;
    float* Xs = sm + 128 * COLS;

    const int tid = threadIdx.x;
    const int r0  = blockIdx.x * 64;

    for (int q = tid; q < 128 * COLS; q += 256) {
        int k = q / COLS, c = q % COLS;
        Ws[q] = (c < NCOUT) ? W[k * NCOUT + c] : 0.f;
    }
    for (int q = tid; q < 64 * 32; q += 256) {
        int r = q >> 5, c4 = q & 31;
        int gr = r0 + r;
        float4 v = make_float4(0.f, 0.f, 0.f, 0.f);
        if (gr < n) {
            v = ((const float4*)(X + (size_t)gr * 128))[c4];
            float s = g_onorm[gr];
            v.x *= s; v.y *= s; v.z *= s; v.w *= s;
        }
        *((float4*)(Xs + r * 132 + c4 * 4)) = v;
    }
    __syncthreads();

    constexpr int CG  = COLS / 4;
    constexpr int RGC = 256 / CG;
    constexpr int RPT = 64 / RGC;
    const int cg = tid % CG;
    const int rg = tid / CG;

    float acc[RPT][4];
#pragma unroll
    for (int i = 0; i < RPT; ++i)
#pragma unroll
        for (int j = 0; j < 4; ++j) acc[i][j] = 0.f;

    const float* xbase = Xs + rg * RPT * 132;
    const float4* wc = ((const float4*)Ws) + cg;
#pragma unroll 4
    for (int k = 0; k < 128; ++k) {
        float4 b = wc[k * CG];
#pragma unroll
        for (int i = 0; i < RPT; ++i) {
            float a = xbase[i * 132 + k];
            acc[i][0] = fmaf(a, b.x, acc[i][0]);
            acc[i][1] = fmaf(a, b.y, acc[i][1]);
            acc[i][2] = fmaf(a, b.z, acc[i][2]);
            acc[i][3] = fmaf(a, b.w, acc[i][3]);
        }
    }

#pragma unroll
    for (int i = 0; i < RPT; ++i) {
        int gr = r0 + rg * RPT + i;
        if (gr >= n) continue;
        int c = cg * 4;
#pragma unroll
        for (int j = 0; j < 4; ++j)
            if (c + j < NCOUT) P[(size_t)gr * NCOUT + c + j] = acc[i][j];
    }
}

// ---------------- CSR aggregation over fp16 P, fused epilogue ----------------
// Half-warp per dst node: 16 lanes x 16B = one 256B fp16 row (16 uint4/row).
template<bool RELU>
__global__ void __launch_bounds__(256)
k_csr_agg128_h(const float* __restrict__ b, float* __restrict__ out, int n) {
    int t    = blockIdx.x * blockDim.x + threadIdx.x;
    int node = t >> 4;
    if (node >= n) return;
    int lane = threadIdx.x & 31;
    int half = (lane >> 4) & 1;
    int sub  = lane & 15;
    const unsigned hmask = 0xFFFFu << (half * 16);

    int beg = g_rowstart[node];
    int end = g_rowstart[node + 1];

    float acc[8];
#pragma unroll
    for (int j = 0; j < 8; ++j) acc[j] = 0.f;

    const uint4* P16 = (const uint4*)g_P16;   // row = 16 uint4 (128 halfs)

    for (int base = beg; base < end; base += 16) {
        int cnt = min(16, end - base);
        int myidx = (sub < cnt) ? g_esrc[base + sub] : 0;
        int j = 0;
        for (; j + 2 <= cnt; j += 2) {
            int s0 = __shfl_sync(hmask, myidx, half * 16 + j);
            int s1 = __shfl_sync(hmask, myidx, half * 16 + j + 1);
            uint4 v0 = P16[(size_t)s0 * 16 + sub];
            uint4 v1 = P16[(size_t)s1 * 16 + sub];
#pragma unroll
            for (int q = 0; q < 4; ++q) {
                uint32_t u0 = (&v0.x)[q];
                uint32_t u1 = (&v1.x)[q];
                float2 f0 = __half22float2(*(__half2*)&u0);
                float2 f1 = __half22float2(*(__half2*)&u1);
                acc[2 * q]     += f0.x + f1.x;
                acc[2 * q + 1] += f0.y + f1.y;
            }
        }
        if (j < cnt) {
            int s = __shfl_sync(hmask, myidx, half * 16 + j);
            uint4 v = P16[(size_t)s * 16 + sub];
#pragma unroll
            for (int q = 0; q < 4; ++q) {
                uint32_t u = (&v.x)[q];
                float2 f = __half22float2(*(__half2*)&u);
                acc[2 * q]     += f.x;
                acc[2 * q + 1] += f.y;
            }
        }
    }

    float sc = g_inorm[node];
    const float4* b4 = ((const float4*)b) + sub * 2;
    float4 bb0 = b4[0];
    float4 bb1 = b4[1];
    float4 r0, r1;
    r0.x = fmaf(acc[0], sc, bb0.x);
    r0.y = fmaf(acc[1], sc, bb0.y);
    r0.z = fmaf(acc[2], sc, bb0.z);
    r0.w = fmaf(acc[3], sc, bb0.w);
    r1.x = fmaf(acc[4], sc, bb1.x);
    r1.y = fmaf(acc[5], sc, bb1.y);
    r1.z = fmaf(acc[6], sc, bb1.z);
    r1.w = fmaf(acc[7], sc, bb1.w);
    if (RELU) {
        r0.x = fmaxf(r0.x, 0.f); r0.y = fmaxf(r0.y, 0.f);
        r0.z = fmaxf(r0.z, 0.f); r0.w = fmaxf(r0.w, 0.f);
        r1.x = fmaxf(r1.x, 0.f); r1.y = fmaxf(r1.y, 0.f);
        r1.z = fmaxf(r1.z, 0.f); r1.w = fmaxf(r1.w, 0.f);
    }
    float4* orow = ((float4*)(out + (size_t)node * 128)) + sub * 2;
    orow[0] = r0;
    orow[1] = r1;
}

// layer-3 aggregation over fp32 P (40 dims)
__global__ void __launch_bounds__(256)
k_csr_agg40(const float* __restrict__ b, float* __restrict__ out, int n) {
    int t = blockIdx.x * blockDim.x + threadIdx.x;
    if (t >= n * 10) return;
    int node = t / 10;
    int g    = t - node * 10;

    int beg = g_rowstart[node];
    int end = g_rowstart[node + 1];

    float4 acc = make_float4(0.f, 0.f, 0.f, 0.f);
    const float4* P4 = (const float4*)g_P;
    int e = beg;
    for (; e + 2 <= end; e += 2) {
        int s0 = g_esrc[e];
        int s1 = g_esrc[e + 1];
        float4 v0 = P4[(size_t)s0 * 10 + g];
        float4 v1 = P4[(size_t)s1 * 10 + g];
        acc.x += v0.x; acc.y += v0.y; acc.z += v0.z; acc.w += v0.w;
        acc.x += v1.x; acc.y += v1.y; acc.z += v1.z; acc.w += v1.w;
    }
    if (e < end) {
        int s = g_esrc[e];
        float4 v = P4[(size_t)s * 10 + g];
        acc.x += v.x; acc.y += v.y; acc.z += v.z; acc.w += v.w;
    }

    float sc  = g_inorm[node];
    float4 bb = ((const float4*)b)[g];
    float4 r;
    r.x = fmaf(acc.x, sc, bb.x);
    r.y = fmaf(acc.y, sc, bb.y);
    r.z = fmaf(acc.z, sc, bb.z);
    r.w = fmaf(acc.w, sc, bb.w);
    ((float4*)(out + (size_t)node * 40))[g] = r;
}

// ---------------- launch ----------------
extern "C" void kernel_launch(void* const* d_in, const int* in_sizes, int n_in,
                              void* d_out, int out_size) {
    const float* feat = (const float*)d_in[0];
    const float* W1   = (const float*)d_in[1];
    const float* b1   = (const float*)d_in[2];
    const float* W2   = (const float*)d_in[3];
    const float* b2   = (const float*)d_in[4];
    const float* W3   = (const float*)d_in[5];
    const float* b3   = (const float*)d_in[6];
    const int*   src  = (const int*)d_in[7];
    const int*   dst  = (const int*)d_in[8];

    const int N  = in_sizes[0] / 128;
    const int nE = in_sizes[7];
    float* out = (float*)d_out;

    float *P = nullptr, *H = nullptr;
    __half* P16 = nullptr;
    void *odeg = nullptr, *ideg = nullptr;
    cudaGetSymbolAddress((void**)&P, g_P);
    cudaGetSymbolAddress((void**)&P16, g_P16);
    cudaGetSymbolAddress((void**)&H, g_H);
    cudaGetSymbolAddress(&odeg, g_outdeg);
    cudaGetSymbolAddress(&ideg, g_indeg);

    const int SMEMV3 = (128 * 132 + 64 * 128) * 4;   // 100352 B
    const int SMEM64 = (128 * 64 + 64 * 132) * 4;    // 66560 B
    cudaFuncSetAttribute(k_gemm128_h, cudaFuncAttributeMaxDynamicSharedMemorySize, SMEMV3);
    cudaFuncSetAttribute(k_gemm<64, 40>, cudaFuncAttributeMaxDynamicSharedMemorySize, SMEM64);

    const int T = 256;
    const int gemmBlocks  = (N + 127) / 128;
    const int gemm3Blocks = (N + 63) / 64;
    const int scanBlocks  = (N + 255) / 256;
    const int aggBlocks   = (N * 16 + T - 1) / T;

    cudaStream_t s1;
    cudaStreamCreateWithFlags(&s1, cudaStreamNonBlocking);
    cudaEvent_t e1, e2;
    cudaEventCreateWithFlags(&e1, cudaEventDisableTiming);
    cudaEventCreateWithFlags(&e2, cudaEventDisableTiming);

    // --- main stream: degrees + norms ---
    cudaMemsetAsync(odeg, 0, (size_t)N * 4, 0);
    cudaMemsetAsync(ideg, 0, (size_t)N * 4, 0);
    k_degree<<<(nE + T - 1) / T, T>>>(src, dst, nE);
    k_norm<<<(N + T - 1) / T, T>>>(N);

    // --- fork: CSR build on s1, GEMM1 on main ---
    cudaEventRecord(e1, 0);
    cudaStreamWaitEvent(s1, e1, 0);
    k_scan1<<<scanBlocks, 256, 0, s1>>>(N);
    k_scan2<<<1, 256, 0, s1>>>(scanBlocks);
    k_scan3<<<scanBlocks, 256, 0, s1>>>(N);
    k_scatter<<<(nE + T - 1) / T, T, 0, s1>>>(src, dst, nE);
    cudaEventRecord(e2, s1);

    k_gemm128_h<<<gemmBlocks, T, SMEMV3>>>(feat, W1, P16, N);

    // --- join ---
    cudaStreamWaitEvent(0, e2, 0);

    // layer 1 aggregation
    k_csr_agg128_h<true><<<aggBlocks, T>>>(b1, H, N);

    // layer 2
    k_gemm128_h<<<gemmBlocks, T, SMEMV3>>>(H, W2, P16, N);
    k_csr_agg128_h<true><<<aggBlocks, T>>>(b2, H, N);

    // layer 3 (fp32 end-to-end)
    k_gemm<64, 40><<<gemm3Blocks, T, SMEM64>>>(H, W3, P, N);
    k_csr_agg40<<<(N * 10 + T - 1) / T, T>>>(b3, out, N);

    cudaStreamCaptureStatus cap = cudaStreamCaptureStatusNone;
    cudaStreamIsCapturing(s1, &cap);
    if (cap == cudaStreamCaptureStatusNone) {
        cudaEventDestroy(e1);
        cudaEventDestroy(e2);
        cudaStreamDestroy(s1);
    }
}

// round 8
// speedup vs baseline: 1.8729x; 1.0002x over previous
#include <cuda_runtime.h>
#include <cuda_fp16.h>
#include <cstdint>

#define NMAX 50000
#define NEMAX 1000000

// ---------------- scratch ----------------
__device__ __align__(16) __half g_P16[(size_t)NMAX * 128];
__device__ __align__(16) float g_P  [(size_t)NMAX * 128];
__device__ __align__(16) float g_H  [(size_t)NMAX * 128];
__device__ __align__(16) int   g_outdeg[NMAX + 8];
__device__ __align__(16) int   g_indeg [NMAX + 8];
__device__ __align__(16) float g_onorm [NMAX + 8];
__device__ __align__(16) float g_inorm [NMAX + 8];
__device__ int g_esrc[NEMAX];
__device__ int g_rowstart[NMAX + 8];
__device__ int g_cursor[NMAX + 8];
__device__ int g_scan[NMAX + 8];
__device__ int g_bsum[512];

// ---------------- packed f32x2 helpers ----------------
__device__ __forceinline__ uint32_t smem_u32(const void* p) {
    uint32_t a;
    asm("{ .reg .u64 t; cvta.to.shared.u64 t, %1; cvt.u32.u64 %0, t; }" : "=r"(a) : "l"(p));
    return a;
}
__device__ __forceinline__ unsigned long long lds_b64(uint32_t a) {
    unsigned long long v;
    asm volatile("ld.shared.b64 %0, [%1];" : "=l"(v) : "r"(a));
    return v;
}
__device__ __forceinline__ uint32_t lds_b32(uint32_t a) {
    uint32_t v;
    asm volatile("ld.shared.b32 %0, [%1];" : "=r"(v) : "r"(a));
    return v;
}
__device__ __forceinline__ unsigned long long dup2(uint32_t x) {
    unsigned long long v;
    asm("mov.b64 %0, {%1, %1};" : "=l"(v) : "r"(x));
    return v;
}
__device__ __forceinline__ void fma2(unsigned long long& d, unsigned long long a, unsigned long long b) {
    asm("fma.rn.f32x2 %0, %1, %2, %0;" : "+l"(d) : "l"(a), "l"(b));
}

// ---------------- degrees / norms (generic: used for src-side and dst-side) --
__global__ void k_degree1(const int* __restrict__ idx, int* __restrict__ deg, int nE) {
    int i = blockIdx.x * blockDim.x + threadIdx.x;
    if (i < nE) atomicAdd(&deg[idx[i]], 1);
}
__global__ void k_norm1(const int* __restrict__ deg, float* __restrict__ nrm, int n) {
    int i = blockIdx.x * blockDim.x + threadIdx.x;
    if (i < n) nrm[i] = rsqrtf(fmaxf((float)deg[i], 1.f));
}

// ---------------- prefix sum -> rowstart / cursor ----------------
__global__ void k_scan1(int n) {
    __shared__ int sm[256];
    int tid = threadIdx.x;
    int i = blockIdx.x * 256 + tid;
    int v = (i < n) ? g_indeg[i] : 0;
    sm[tid] = v;
    __syncthreads();
    for (int off = 1; off < 256; off <<= 1) {
        int t = 0;
        if (tid >= off) t = sm[tid - off];
        __syncthreads();
        if (tid >= off) sm[tid] += t;
        __syncthreads();
    }
    if (i < n) g_scan[i] = sm[tid];
    if (tid == 255) g_bsum[blockIdx.x] = sm[255];
}
__global__ void k_scan2(int nb) {
    __shared__ int sm[256];
    int tid = threadIdx.x;
    int v = (tid < nb) ? g_bsum[tid] : 0;
    sm[tid] = v;
    __syncthreads();
    for (int off = 1; off < 256; off <<= 1) {
        int t = 0;
        if (tid >= off) t = sm[tid - off];
        __syncthreads();
        if (tid >= off) sm[tid] += t;
        __syncthreads();
    }
    if (tid < nb) g_bsum[tid] = sm[tid] - v;
}
__global__ void k_scan3(int n) {
    int i = blockIdx.x * blockDim.x + threadIdx.x;
    if (i < n) {
        int incl = g_scan[i] + g_bsum[i >> 8];
        int start = incl - g_indeg[i];
        g_rowstart[i] = start;
        g_cursor[i]   = start;
        if (i == n - 1) g_rowstart[n] = incl;
    }
}
__global__ void k_scatter(const int* __restrict__ src, const int* __restrict__ dst, int nE) {
    int i = blockIdx.x * blockDim.x + threadIdx.x;
    if (i < nE) {
        int d = dst[i];
        int pos = atomicAdd(&g_cursor[d], 1);
        g_esrc[pos] = src[i];
    }
}

// ---------------- GEMM 128x128 with packed f32x2 FMA, fp16 output ----------------
__global__ void __launch_bounds__(256)
k_gemm128_h(const float* __restrict__ X, const float* __restrict__ W,
            __half* __restrict__ P, int n) {
    extern __shared__ float sm[];
    float* Xs = sm;                 // [128][132]
    float* Ws = sm + 128 * 132;     // [64][128]

    const uint32_t smem_base = smem_u32(sm);
    const uint32_t WS_OFF = 128 * 132 * 4;

    const int tid = threadIdx.x;
    const int r0  = blockIdx.x * 128;
    const int tx  = tid & 15;
    const int ty  = tid >> 4;

    for (int q = tid; q < 128 * 32; q += 256) {
        int r = q >> 5, c4 = q & 31;
        int gr = r0 + r;
        float4 v = make_float4(0.f, 0.f, 0.f, 0.f);
        if (gr < n) {
            v = ((const float4*)(X + (size_t)gr * 128))[c4];
            float s = g_onorm[gr];
            v.x *= s; v.y *= s; v.z *= s; v.w *= s;
        }
        *((float4*)(Xs + r * 132 + c4 * 4)) = v;
    }

    unsigned long long acc[8][4];
#pragma unroll
    for (int i = 0; i < 8; ++i)
#pragma unroll
        for (int j = 0; j < 4; ++j) acc[i][j] = 0ull;

    const uint32_t xrow0 = smem_base + (uint32_t)(ty * 8 * 132) * 4;
    const uint32_t wbase = smem_base + WS_OFF + (uint32_t)tx * 16;

    for (int half = 0; half < 2; ++half) {
        __syncthreads();
        for (int q = tid; q < 64 * 32; q += 256)
            ((float4*)Ws)[q] = ((const float4*)W)[half * 2048 + q];
        __syncthreads();

        const uint32_t xh = xrow0 + (uint32_t)(half * 64) * 4;
#pragma unroll 2
        for (int kk = 0; kk < 64; ++kk) {
            uint32_t wb = wbase + (uint32_t)kk * 512;
            unsigned long long b0 = lds_b64(wb);
            unsigned long long b1 = lds_b64(wb + 8);
            unsigned long long b2 = lds_b64(wb + 256);
            unsigned long long b3 = lds_b64(wb + 264);
#pragma unroll
            for (int i = 0; i < 8; ++i) {
                unsigned long long ap = dup2(lds_b32(xh + (uint32_t)(i * 132 + kk) * 4));
                fma2(acc[i][0], ap, b0);
                fma2(acc[i][1], ap, b1);
                fma2(acc[i][2], ap, b2);
                fma2(acc[i][3], ap, b3);
            }
        }
    }

#pragma unroll
    for (int i = 0; i < 8; ++i) {
        int gr = r0 + ty * 8 + i;
        if (gr >= n) continue;
        __half* prow = P + (size_t)gr * 128;
        float2 p0 = *(float2*)&acc[i][0];
        float2 p1 = *(float2*)&acc[i][1];
        float2 p2 = *(float2*)&acc[i][2];
        float2 p3 = *(float2*)&acc[i][3];
        __half2 h0 = __floats2half2_rn(p0.x, p0.y);
        __half2 h1 = __floats2half2_rn(p1.x, p1.y);
        __half2 h2 = __floats2half2_rn(p2.x, p2.y);
        __half2 h3 = __floats2half2_rn(p3.x, p3.y);
        uint2 w0; w0.x = *(uint32_t*)&h0; w0.y = *(uint32_t*)&h1;
        uint2 w1; w1.x = *(uint32_t*)&h2; w1.y = *(uint32_t*)&h3;
        *(uint2*)(prow + 4 * tx)      = w0;
        *(uint2*)(prow + 64 + 4 * tx) = w1;
    }
}

// ---------------- GEMM for layer 3 (128 -> 40), fp32 ----------------
template<int COLS, int NCOUT>
__global__ void __launch_bounds__(256)
k_gemm(const float* __restrict__ X, const float* __restrict__ W,
       float* __restrict__ P, int n) {
    extern __shared__ float sm[];
    float* Ws = sm;
    float* Xs = sm + 128 * COLS;

    const int tid = threadIdx.x;
    const int r0  = blockIdx.x * 64;

    for (int q = tid; q < 128 * COLS; q += 256) {
        int k = q / COLS, c = q % COLS;
        Ws[q] = (c < NCOUT) ? W[k * NCOUT + c] : 0.f;
    }
    for (int q = tid; q < 64 * 32; q += 256) {
        int r = q >> 5, c4 = q & 31;
        int gr = r0 + r;
        float4 v = make_float4(0.f, 0.f, 0.f, 0.f);
        if (gr < n) {
            v = ((const float4*)(X + (size_t)gr * 128))[c4];
            float s = g_onorm[gr];
            v.x *= s; v.y *= s; v.z *= s; v.w *= s;
        }
        *((float4*)(Xs + r * 132 + c4 * 4)) = v;
    }
    __syncthreads();

    constexpr int CG  = COLS / 4;
    constexpr int RGC = 256 / CG;
    constexpr int RPT = 64 / RGC;
    const int cg = tid % CG;
    const int rg = tid / CG;

    float acc[RPT][4];
#pragma unroll
    for (int i = 0; i < RPT; ++i)
#pragma unroll
        for (int j = 0; j < 4; ++j) acc[i][j] = 0.f;

    const float* xbase = Xs + rg * RPT * 132;
    const float4* wc = ((const float4*)Ws) + cg;
#pragma unroll 4
    for (int k = 0; k < 128; ++k) {
        float4 b = wc[k * CG];
#pragma unroll
        for (int i = 0; i < RPT; ++i) {
            float a = xbase[i * 132 + k];
            acc[i][0] = fmaf(a, b.x, acc[i][0]);
            acc[i][1] = fmaf(a, b.y, acc[i][1]);
            acc[i][2] = fmaf(a, b.z, acc[i][2]);
            acc[i][3] = fmaf(a, b.w, acc[i][3]);
        }
    }

#pragma unroll
    for (int i = 0; i < RPT; ++i) {
        int gr = r0 + rg * RPT + i;
        if (gr >= n) continue;
        int c = cg * 4;
#pragma unroll
        for (int j = 0; j < 4; ++j)
            if (c + j < NCOUT) P[(size_t)gr * NCOUT + c + j] = acc[i][j];
    }
}

// ---------------- CSR aggregation over fp16 P, full warp per node ----------------
// Warp per node; lane = (grp = lane>>4, sub = lane&15). Per iteration the warp
// loads TWO fp16 rows (grp selects edge j or j+1); combine halves via shfl_xor(16).
template<bool RELU>
__global__ void __launch_bounds__(256)
k_csr_agg128_h(const float* __restrict__ b, float* __restrict__ out, int n) {
    int w    = (blockIdx.x * blockDim.x + threadIdx.x) >> 5;
    if (w >= n) return;
    int lane = threadIdx.x & 31;
    int sub  = lane & 15;
    int grp  = lane >> 4;

    int beg = g_rowstart[w];
    int end = g_rowstart[w + 1];

    float acc[8];
#pragma unroll
    for (int j = 0; j < 8; ++j) acc[j] = 0.f;

    const uint4* P16 = (const uint4*)g_P16;   // row = 16 uint4

    for (int base = beg; base < end; base += 32) {
        int cnt = min(32, end - base);
        int myidx = (lane < cnt) ? g_esrc[base + lane] : 0;
        int j = 0;
        for (; j + 4 <= cnt; j += 4) {
            int sA = __shfl_sync(0xffffffffu, myidx, j + grp);
            int sB = __shfl_sync(0xffffffffu, myidx, j + 2 + grp);
            uint4 vA = P16[(size_t)sA * 16 + sub];
            uint4 vB = P16[(size_t)sB * 16 + sub];
#pragma unroll
            for (int q = 0; q < 4; ++q) {
                uint32_t uA = (&vA.x)[q];
                uint32_t uB = (&vB.x)[q];
                float2 fA = __half22float2(*(__half2*)&uA);
                float2 fB = __half22float2(*(__half2*)&uB);
                acc[2 * q]     += fA.x + fB.x;
                acc[2 * q + 1] += fA.y + fB.y;
            }
        }
        for (; j + 2 <= cnt; j += 2) {
            int s = __shfl_sync(0xffffffffu, myidx, j + grp);
            uint4 v = P16[(size_t)s * 16 + sub];
#pragma unroll
            for (int q = 0; q < 4; ++q) {
                uint32_t u = (&v.x)[q];
                float2 f = __half22float2(*(__half2*)&u);
                acc[2 * q]     += f.x;
                acc[2 * q + 1] += f.y;
            }
        }
        if (j < cnt) {
            int s = __shfl_sync(0xffffffffu, myidx, j);
            if (grp == 0) {
                uint4 v = P16[(size_t)s * 16 + sub];
#pragma unroll
                for (int q = 0; q < 4; ++q) {
                    uint32_t u = (&v.x)[q];
                    float2 f = __half22float2(*(__half2*)&u);
                    acc[2 * q]     += f.x;
                    acc[2 * q + 1] += f.y;
                }
            }
        }
    }

    // combine the two edge-parity halves
#pragma unroll
    for (int q = 0; q < 8; ++q)
        acc[q] += __shfl_xor_sync(0xffffffffu, acc[q], 16);

    if (grp == 0) {
        float sc = g_inorm[w];
        const float4* b4 = ((const float4*)b) + sub * 2;
        float4 bb0 = b4[0];
        float4 bb1 = b4[1];
        float4 r0, r1;
        r0.x = fmaf(acc[0], sc, bb0.x);
        r0.y = fmaf(acc[1], sc, bb0.y);
        r0.z = fmaf(acc[2], sc, bb0.z);
        r0.w = fmaf(acc[3], sc, bb0.w);
        r1.x = fmaf(acc[4], sc, bb1.x);
        r1.y = fmaf(acc[5], sc, bb1.y);
        r1.z = fmaf(acc[6], sc, bb1.z);
        r1.w = fmaf(acc[7], sc, bb1.w);
        if (RELU) {
            r0.x = fmaxf(r0.x, 0.f); r0.y = fmaxf(r0.y, 0.f);
            r0.z = fmaxf(r0.z, 0.f); r0.w = fmaxf(r0.w, 0.f);
            r1.x = fmaxf(r1.x, 0.f); r1.y = fmaxf(r1.y, 0.f);
            r1.z = fmaxf(r1.z, 0.f); r1.w = fmaxf(r1.w, 0.f);
        }
        float4* orow = ((float4*)(out + (size_t)w * 128)) + sub * 2;
        orow[0] = r0;
        orow[1] = r1;
    }
}

// layer-3 aggregation over fp32 P (40 dims)
__global__ void __launch_bounds__(256)
k_csr_agg40(const float* __restrict__ b, float* __restrict__ out, int n) {
    int t = blockIdx.x * blockDim.x + threadIdx.x;
    if (t >= n * 10) return;
    int node = t / 10;
    int g    = t - node * 10;

    int beg = g_rowstart[node];
    int end = g_rowstart[node + 1];

    float4 acc = make_float4(0.f, 0.f, 0.f, 0.f);
    const float4* P4 = (const float4*)g_P;
    int e = beg;
    for (; e + 2 <= end; e += 2) {
        int s0 = g_esrc[e];
        int s1 = g_esrc[e + 1];
        float4 v0 = P4[(size_t)s0 * 10 + g];
        float4 v1 = P4[(size_t)s1 * 10 + g];
        acc.x += v0.x; acc.y += v0.y; acc.z += v0.z; acc.w += v0.w;
        acc.x += v1.x; acc.y += v1.y; acc.z += v1.z; acc.w += v1.w;
    }
    if (e < end) {
        int s = g_esrc[e];
        float4 v = P4[(size_t)s * 10 + g];
        acc.x += v.x; acc.y += v.y; acc.z += v.z; acc.w += v.w;
    }

    float sc  = g_inorm[node];
    float4 bb = ((const float4*)b)[g];
    float4 r;
    r.x = fmaf(acc.x, sc, bb.x);
    r.y = fmaf(acc.y, sc, bb.y);
    r.z = fmaf(acc.z, sc, bb.z);
    r.w = fmaf(acc.w, sc, bb.w);
    ((float4*)(out + (size_t)node * 40))[g] = r;
}

// ---------------- launch ----------------
extern "C" void kernel_launch(void* const* d_in, const int* in_sizes, int n_in,
                              void* d_out, int out_size) {
    const float* feat = (const float*)d_in[0];
    const float* W1   = (const float*)d_in[1];
    const float* b1   = (const float*)d_in[2];
    const float* W2   = (const float*)d_in[3];
    const float* b2   = (const float*)d_in[4];
    const float* W3   = (const float*)d_in[5];
    const float* b3   = (const float*)d_in[6];
    const int*   src  = (const int*)d_in[7];
    const int*   dst  = (const int*)d_in[8];

    const int N  = in_sizes[0] / 128;
    const int nE = in_sizes[7];
    float* out = (float*)d_out;

    float *P = nullptr, *H = nullptr, *onorm = nullptr, *inorm = nullptr;
    __half* P16 = nullptr;
    int *odeg = nullptr, *ideg = nullptr;
    cudaGetSymbolAddress((void**)&P, g_P);
    cudaGetSymbolAddress((void**)&P16, g_P16);
    cudaGetSymbolAddress((void**)&H, g_H);
    cudaGetSymbolAddress((void**)&odeg, g_outdeg);
    cudaGetSymbolAddress((void**)&ideg, g_indeg);
    cudaGetSymbolAddress((void**)&onorm, g_onorm);
    cudaGetSymbolAddress((void**)&inorm, g_inorm);

    const int SMEMV3 = (128 * 132 + 64 * 128) * 4;   // 100352 B
    const int SMEM64 = (128 * 64 + 64 * 132) * 4;    // 66560 B
    cudaFuncSetAttribute(k_gemm128_h, cudaFuncAttributeMaxDynamicSharedMemorySize, SMEMV3);
    cudaFuncSetAttribute(k_gemm<64, 40>, cudaFuncAttributeMaxDynamicSharedMemorySize, SMEM64);

    const int T = 256;
    const int gemmBlocks  = (N + 127) / 128;
    const int gemm3Blocks = (N + 63) / 64;
    const int scanBlocks  = (N + 255) / 256;
    const int aggBlocks   = (N * 32 + T - 1) / T;
    const int eBlocks     = (nE + T - 1) / T;

    cudaStream_t s1;
    cudaStreamCreateWithFlags(&s1, cudaStreamNonBlocking);
    cudaEvent_t e0, e2;
    cudaEventCreateWithFlags(&e0, cudaEventDisableTiming);
    cudaEventCreateWithFlags(&e2, cudaEventDisableTiming);

    // --- fork at t=0: side stream owns the dst-side (indeg/inorm/CSR) ---
    cudaEventRecord(e0, 0);
    cudaStreamWaitEvent(s1, e0, 0);

    cudaMemsetAsync(ideg, 0, (size_t)N * 4, s1);
    k_degree1<<<eBlocks, T, 0, s1>>>(dst, ideg, nE);
    k_norm1<<<(N + T - 1) / T, T, 0, s1>>>(ideg, inorm, N);
    k_scan1<<<scanBlocks, 256, 0, s1>>>(N);
    k_scan2<<<1, 256, 0, s1>>>(scanBlocks);
    k_scan3<<<scanBlocks, 256, 0, s1>>>(N);
    k_scatter<<<eBlocks, T, 0, s1>>>(src, dst, nE);
    cudaEventRecord(e2, s1);

    // --- main stream: src-side (outdeg/onorm) + GEMM1 ---
    cudaMemsetAsync(odeg, 0, (size_t)N * 4, 0);
    k_degree1<<<eBlocks, T>>>(src, odeg, nE);
    k_norm1<<<(N + T - 1) / T, T>>>(odeg, onorm, N);
    k_gemm128_h<<<gemmBlocks, T, SMEMV3>>>(feat, W1, P16, N);

    // --- join ---
    cudaStreamWaitEvent(0, e2, 0);

    // layer 1 aggregation
    k_csr_agg128_h<true><<<aggBlocks, T>>>(b1, H, N);

    // layer 2
    k_gemm128_h<<<gemmBlocks, T, SMEMV3>>>(H, W2, P16, N);
    k_csr_agg128_h<true><<<aggBlocks, T>>>(b2, H, N);

    // layer 3 (fp32 end-to-end)
    k_gemm<64, 40><<<gemm3Blocks, T, SMEM64>>>(H, W3, P, N);
    k_csr_agg40<<<(N * 10 + T - 1) / T, T>>>(b3, out, N);

    cudaStreamCaptureStatus cap = cudaStreamCaptureStatusNone;
    cudaStreamIsCapturing(s1, &cap);
    if (cap == cudaStreamCaptureStatusNone) {
        cudaEventDestroy(e0);
        cudaEventDestroy(e2);
        cudaStreamDestroy(s1);
    }
}